// round 13
// baseline (speedup 1.0000x reference)
#include <cuda_runtime.h>
#include <cuda_bf16.h>
#include <cstdint>
#include <stdint.h>
#include <math.h>

// ---------------------------------------------------------------------------
// MoE router, single kernel, pure-LDG streaming (no smem staging).
// logits = hidden[16384,4096] @ gate_w[8,4096]^T
// softmax -> top2 -> normalized weights; aux loss = 0.01*E*sum(f*P)
// Output (float32, flat): weights[T,2] | experts[T,2] | logits[T,8] | aux
//
// Design: gate lives in L1 (228KB, no smem carveout); hidden streamed with
// __ldcs (evict-first). 3 CTAs/SM x 4 warps; 4 tokens/warp.
// ---------------------------------------------------------------------------

#define T_TOK     16384
#define HDIM      4096
#define NEXP      8
#define TOK_WARP  4
#define NWARP     4
#define NTHREAD   128
#define TOK_BLK   (TOK_WARP * NWARP)    /* 16 */
#define NBLOCK    (T_TOK / TOK_BLK)     /* 1024 */
#define CHUNK     256
#define NCHUNK    (HDIM / CHUNK)        /* 16 */

#define OUT_W     0
#define OUT_IDX   (T_TOK * 2)
#define OUT_LOG   (T_TOK * 4)
#define OUT_AUX   (T_TOK * 12)

// Tie tolerance + Kahan logits are a proven pair (R5/R7/R9/R10/R11 pass;
// without Kahan one knife-edge token flips). Arithmetic is bit-identical
// to those passing kernels (same chunk order, same lane mapping).
#define TIE_TOL   5e-7f

__device__ float    g_Psum[NEXP];
__device__ unsigned g_Cnt[NEXP];
__device__ unsigned g_done;

__global__ void __launch_bounds__(NTHREAD, 3) router_main_kernel(
    const float* __restrict__ hs,    // [T, H]
    const float* __restrict__ gw,    // [E, H]
    float* __restrict__ out)
{
    __shared__ float    sPsum[NEXP];
    __shared__ unsigned sCnt[NEXP];

    const int tid  = threadIdx.x;
    const int warp = tid >> 5;
    const int lane = tid & 31;
    const int row0 = warp * TOK_WARP;
    const size_t tokBase = (size_t)blockIdx.x * TOK_BLK;

    if (tid < NEXP) { sPsum[tid] = 0.0f; sCnt[tid] = 0u; }
    __syncthreads();

    // Kahan-compensated fp32 accumulators per (expert, token)
    float accS[NEXP][TOK_WARP];
    float accC[NEXP][TOK_WARP];
    #pragma unroll
    for (int e = 0; e < NEXP; e++)
        #pragma unroll
        for (int t = 0; t < TOK_WARP; t++) { accS[e][t] = 0.0f; accC[e][t] = 0.0f; }

    // hidden base for this warp's 4 tokens
    const float* hp = hs + (tokBase + row0) * HDIM + lane * 4;

    for (int c = 0; c < NCHUNK; c++) {
        // hidden: batch all 8 LDG.128 first (MLP), streaming hint keeps L1
        // free for the gate.
        float4 xa[TOK_WARP], xb[TOK_WARP];
        {
            const float* hc = hp + c * CHUNK;
            #pragma unroll
            for (int t = 0; t < TOK_WARP; t++) {
                xa[t] = __ldcs((const float4*)(hc + (size_t)t * HDIM));
                xb[t] = __ldcs((const float4*)(hc + (size_t)t * HDIM + 128));
            }
        }

        // gate regs: 8 experts x 8 h-values per lane (L1-resident)
        float4 g0[NEXP], g1[NEXP];
        {
            const float* gp = gw + c * CHUNK + lane * 4;
            #pragma unroll
            for (int e = 0; e < NEXP; e++) {
                g0[e] = *(const float4*)(gp + e * HDIM);
                g1[e] = *(const float4*)(gp + e * HDIM + 128);
            }
        }

        #pragma unroll
        for (int t = 0; t < TOK_WARP; t++) {
            #pragma unroll
            for (int e = 0; e < NEXP; e++) {
                float p = __fmul_rn(xa[t].x, g0[e].x);
                p = __fmaf_rn(xa[t].y, g0[e].y, p);
                p = __fmaf_rn(xa[t].z, g0[e].z, p);
                p = __fmaf_rn(xa[t].w, g0[e].w, p);
                p = __fmaf_rn(xb[t].x, g1[e].x, p);
                p = __fmaf_rn(xb[t].y, g1[e].y, p);
                p = __fmaf_rn(xb[t].z, g1[e].z, p);
                p = __fmaf_rn(xb[t].w, g1[e].w, p);
                float y  = __fsub_rn(p, accC[e][t]);
                float t2 = __fadd_rn(accS[e][t], y);
                accC[e][t] = __fsub_rn(__fsub_rn(t2, accS[e][t]), y);
                accS[e][t] = t2;
            }
        }
    }

    // ---- cross-lane reduction in fp64 (exact); owning lane keeps result
    float l[NEXP];
    #pragma unroll
    for (int e = 0; e < NEXP; e++) {
        #pragma unroll
        for (int t = 0; t < TOK_WARP; t++) {
            double v = (double)accS[e][t] + (double)accC[e][t];
            v += __shfl_xor_sync(0xFFFFFFFFu, v, 16);
            v += __shfl_xor_sync(0xFFFFFFFFu, v, 8);
            v += __shfl_xor_sync(0xFFFFFFFFu, v, 4);
            v += __shfl_xor_sync(0xFFFFFFFFu, v, 2);
            v += __shfl_xor_sync(0xFFFFFFFFu, v, 1);
            if (lane == t) l[e] = (float)v;
        }
    }

    // ---- epilogue: lanes 0..3 each finish one token
    if (lane < TOK_WARP) {
        const size_t tok = tokBase + row0 + lane;

        float* lg = out + OUT_LOG + tok * NEXP;
        ((float4*)lg)[0] = make_float4(l[0], l[1], l[2], l[3]);
        ((float4*)lg)[1] = make_float4(l[4], l[5], l[6], l[7]);

        float m = l[0];
        #pragma unroll
        for (int e = 1; e < NEXP; e++) m = fmaxf(m, l[e]);
        float p[NEXP], sum = 0.0f;
        #pragma unroll
        for (int e = 0; e < NEXP; e++) { p[e] = expf(l[e] - m); sum += p[e]; }
        const float inv = 1.0f / sum;

        int i1 = 0;
        #pragma unroll
        for (int e = 1; e < NEXP; e++) if (p[e] > p[i1] + TIE_TOL) i1 = e;
        int i2 = (i1 == 0) ? 1 : 0;
        #pragma unroll
        for (int e = 0; e < NEXP; e++)
            if (e != i1 && e != i2 && p[e] > p[i2] + TIE_TOL) i2 = e;
        const float v1 = p[i1];
        const float v2 = p[i2];

        const float winv = 1.0f / (v1 + v2);
        out[OUT_W   + tok * 2 + 0] = v1 * winv;
        out[OUT_W   + tok * 2 + 1] = v2 * winv;
        out[OUT_IDX + tok * 2 + 0] = (float)i1;
        out[OUT_IDX + tok * 2 + 1] = (float)i2;

        #pragma unroll
        for (int e = 0; e < NEXP; e++) atomicAdd(&sPsum[e], p[e] * inv);
        atomicAdd(&sCnt[i1], 1u);
    }
    __syncthreads();

    // ---- aux-loss: push partials; last block finalizes + resets scratch
    if (tid == 0) {
        #pragma unroll
        for (int e = 0; e < NEXP; e++) {
            atomicAdd(&g_Psum[e], sPsum[e]);
            atomicAdd(&g_Cnt[e],  sCnt[e]);
        }
        __threadfence();
        const unsigned prev = atomicAdd(&g_done, 1u);
        if (prev == NBLOCK - 1) {
            float s = 0.0f;
            const float invT = 1.0f / (float)T_TOK;
            #pragma unroll
            for (int e = 0; e < NEXP; e++) {
                const float P = atomicAdd(&g_Psum[e], 0.0f) * invT;
                const float f = (float)atomicAdd(&g_Cnt[e], 0u) * invT;
                s += f * P;
            }
            out[OUT_AUX] = 0.01f * (float)NEXP * s;
            #pragma unroll
            for (int e = 0; e < NEXP; e++) { g_Psum[e] = 0.0f; g_Cnt[e] = 0u; }
            __threadfence();
            g_done = 0u;
        }
    }
}

extern "C" void kernel_launch(void* const* d_in, const int* in_sizes, int n_in,
                              void* d_out, int out_size) {
    const float* hs = (const float*)d_in[0];
    const float* gw = (const float*)d_in[1];
    if (n_in >= 2 && in_sizes[0] < in_sizes[1]) {
        const float* tmp = hs; hs = gw; gw = tmp;
    }
    float* out = (float*)d_out;

    router_main_kernel<<<NBLOCK, NTHREAD>>>(hs, gw, out);
}

// round 14
// speedup vs baseline: 1.0909x; 1.0909x over previous
#include <cuda_runtime.h>
#include <cuda_bf16.h>
#include <cstdint>
#include <stdint.h>
#include <math.h>

// ---------------------------------------------------------------------------
// MoE router, single kernel, register-double-buffered LDG streaming.
// logits = hidden[16384,4096] @ gate_w[8,4096]^T
// softmax -> top2 -> normalized weights; aux loss = 0.01*E*sum(f*P)
// Output (float32, flat): weights[T,2] | experts[T,2] | logits[T,8] | aux
//
// Key idea this round: prefetch chunk c+1's hidden values into a second
// register buffer BEFORE computing chunk c, so DRAM latency overlaps the
// FMA phase (previous designs serialized load->compute per chunk).
// ---------------------------------------------------------------------------

#define T_TOK     16384
#define HDIM      4096
#define NEXP      8
#define TOK_WARP  4
#define NWARP     4
#define NTHREAD   128
#define TOK_BLK   (TOK_WARP * NWARP)    /* 16 */
#define NBLOCK    (T_TOK / TOK_BLK)     /* 1024 */
#define CHUNK     256
#define NCHUNK    (HDIM / CHUNK)        /* 16 */

#define OUT_W     0
#define OUT_IDX   (T_TOK * 2)
#define OUT_LOG   (T_TOK * 4)
#define OUT_AUX   (T_TOK * 12)

// Tie tolerance + Kahan logits are a proven pair (R5/R7/R9-R12 pass; without
// Kahan one knife-edge token flips). Arithmetic is bit-identical to those
// passing kernels (same chunk order, same lane mapping).
#define TIE_TOL   5e-7f

__device__ float    g_Psum[NEXP];
__device__ unsigned g_Cnt[NEXP];
__device__ unsigned g_done;

__device__ __forceinline__ void load_hidden(const float* hp, int c,
                                            float4* xa, float4* xb) {
    const float* hc = hp + c * CHUNK;
    #pragma unroll
    for (int t = 0; t < TOK_WARP; t++) {
        xa[t] = __ldcs((const float4*)(hc + (size_t)t * HDIM));
        xb[t] = __ldcs((const float4*)(hc + (size_t)t * HDIM + 128));
    }
}

__device__ __forceinline__ void compute_chunk(const float* __restrict__ gw,
                                              int c, int lane,
                                              const float4* xa, const float4* xb,
                                              float accS[NEXP][TOK_WARP],
                                              float accC[NEXP][TOK_WARP]) {
    float4 g0[NEXP], g1[NEXP];
    const float* gp = gw + c * CHUNK + lane * 4;
    #pragma unroll
    for (int e = 0; e < NEXP; e++) {
        g0[e] = *(const float4*)(gp + e * HDIM);
        g1[e] = *(const float4*)(gp + e * HDIM + 128);
    }
    #pragma unroll
    for (int t = 0; t < TOK_WARP; t++) {
        #pragma unroll
        for (int e = 0; e < NEXP; e++) {
            float p = __fmul_rn(xa[t].x, g0[e].x);
            p = __fmaf_rn(xa[t].y, g0[e].y, p);
            p = __fmaf_rn(xa[t].z, g0[e].z, p);
            p = __fmaf_rn(xa[t].w, g0[e].w, p);
            p = __fmaf_rn(xb[t].x, g1[e].x, p);
            p = __fmaf_rn(xb[t].y, g1[e].y, p);
            p = __fmaf_rn(xb[t].z, g1[e].z, p);
            p = __fmaf_rn(xb[t].w, g1[e].w, p);
            float y  = __fsub_rn(p, accC[e][t]);
            float t2 = __fadd_rn(accS[e][t], y);
            accC[e][t] = __fsub_rn(__fsub_rn(t2, accS[e][t]), y);
            accS[e][t] = t2;
        }
    }
}

__global__ void __launch_bounds__(NTHREAD, 2) router_main_kernel(
    const float* __restrict__ hs,    // [T, H]
    const float* __restrict__ gw,    // [E, H]
    float* __restrict__ out)
{
    __shared__ float    sPsum[NEXP];
    __shared__ unsigned sCnt[NEXP];

    const int tid  = threadIdx.x;
    const int warp = tid >> 5;
    const int lane = tid & 31;
    const int row0 = warp * TOK_WARP;
    const size_t tokBase = (size_t)blockIdx.x * TOK_BLK;

    if (tid < NEXP) { sPsum[tid] = 0.0f; sCnt[tid] = 0u; }
    __syncthreads();

    float accS[NEXP][TOK_WARP];
    float accC[NEXP][TOK_WARP];
    #pragma unroll
    for (int e = 0; e < NEXP; e++)
        #pragma unroll
        for (int t = 0; t < TOK_WARP; t++) { accS[e][t] = 0.0f; accC[e][t] = 0.0f; }

    const float* hp = hs + (tokBase + row0) * HDIM + lane * 4;

    // register double buffers for the hidden stream
    float4 Aa[TOK_WARP], Ab[TOK_WARP];   // buffer A
    float4 Ba[TOK_WARP], Bb[TOK_WARP];   // buffer B

    load_hidden(hp, 0, Aa, Ab);          // prologue: chunk 0 -> A

    #pragma unroll 1
    for (int c = 0; c < NCHUNK; c += 2) {
        // even body: prefetch c+1 -> B, compute c from A
        load_hidden(hp, c + 1, Ba, Bb);                 // c+1 <= 15 always
        compute_chunk(gw, c, lane, Aa, Ab, accS, accC);

        // odd body: prefetch c+2 -> A (if any), compute c+1 from B
        if (c + 2 < NCHUNK) load_hidden(hp, c + 2, Aa, Ab);
        compute_chunk(gw, c + 1, lane, Ba, Bb, accS, accC);
    }

    // ---- cross-lane reduction in fp64 (exact); owning lane keeps result
    float l[NEXP];
    #pragma unroll
    for (int e = 0; e < NEXP; e++) {
        #pragma unroll
        for (int t = 0; t < TOK_WARP; t++) {
            double v = (double)accS[e][t] + (double)accC[e][t];
            v += __shfl_xor_sync(0xFFFFFFFFu, v, 16);
            v += __shfl_xor_sync(0xFFFFFFFFu, v, 8);
            v += __shfl_xor_sync(0xFFFFFFFFu, v, 4);
            v += __shfl_xor_sync(0xFFFFFFFFu, v, 2);
            v += __shfl_xor_sync(0xFFFFFFFFu, v, 1);
            if (lane == t) l[e] = (float)v;
        }
    }

    // ---- epilogue: lanes 0..3 each finish one token
    if (lane < TOK_WARP) {
        const size_t tok = tokBase + row0 + lane;

        float* lg = out + OUT_LOG + tok * NEXP;
        ((float4*)lg)[0] = make_float4(l[0], l[1], l[2], l[3]);
        ((float4*)lg)[1] = make_float4(l[4], l[5], l[6], l[7]);

        float m = l[0];
        #pragma unroll
        for (int e = 1; e < NEXP; e++) m = fmaxf(m, l[e]);
        float p[NEXP], sum = 0.0f;
        #pragma unroll
        for (int e = 0; e < NEXP; e++) { p[e] = expf(l[e] - m); sum += p[e]; }
        const float inv = 1.0f / sum;

        int i1 = 0;
        #pragma unroll
        for (int e = 1; e < NEXP; e++) if (p[e] > p[i1] + TIE_TOL) i1 = e;
        int i2 = (i1 == 0) ? 1 : 0;
        #pragma unroll
        for (int e = 0; e < NEXP; e++)
            if (e != i1 && e != i2 && p[e] > p[i2] + TIE_TOL) i2 = e;
        const float v1 = p[i1];
        const float v2 = p[i2];

        const float winv = 1.0f / (v1 + v2);
        out[OUT_W   + tok * 2 + 0] = v1 * winv;
        out[OUT_W   + tok * 2 + 1] = v2 * winv;
        out[OUT_IDX + tok * 2 + 0] = (float)i1;
        out[OUT_IDX + tok * 2 + 1] = (float)i2;

        #pragma unroll
        for (int e = 0; e < NEXP; e++) atomicAdd(&sPsum[e], p[e] * inv);
        atomicAdd(&sCnt[i1], 1u);
    }
    __syncthreads();

    // ---- aux-loss: push partials; last block finalizes + resets scratch
    if (tid == 0) {
        #pragma unroll
        for (int e = 0; e < NEXP; e++) {
            atomicAdd(&g_Psum[e], sPsum[e]);
            atomicAdd(&g_Cnt[e],  sCnt[e]);
        }
        __threadfence();
        const unsigned prev = atomicAdd(&g_done, 1u);
        if (prev == NBLOCK - 1) {
            float s = 0.0f;
            const float invT = 1.0f / (float)T_TOK;
            #pragma unroll
            for (int e = 0; e < NEXP; e++) {
                const float P = atomicAdd(&g_Psum[e], 0.0f) * invT;
                const float f = (float)atomicAdd(&g_Cnt[e], 0u) * invT;
                s += f * P;
            }
            out[OUT_AUX] = 0.01f * (float)NEXP * s;
            #pragma unroll
            for (int e = 0; e < NEXP; e++) { g_Psum[e] = 0.0f; g_Cnt[e] = 0u; }
            __threadfence();
            g_done = 0u;
        }
    }
}

extern "C" void kernel_launch(void* const* d_in, const int* in_sizes, int n_in,
                              void* d_out, int out_size) {
    const float* hs = (const float*)d_in[0];
    const float* gw = (const float*)d_in[1];
    if (n_in >= 2 && in_sizes[0] < in_sizes[1]) {
        const float* tmp = hs; hs = gw; gw = tmp;
    }
    float* out = (float*)d_out;

    router_main_kernel<<<NBLOCK, NTHREAD>>>(hs, gw, out);
}

// round 15
// speedup vs baseline: 1.2631x; 1.1578x over previous
#include <cuda_runtime.h>
#include <cuda_bf16.h>
#include <cstdint>
#include <stdint.h>
#include <math.h>

// ---------------------------------------------------------------------------
// MoE router, single kernel, occupancy-first pure-LDG design.
// logits = hidden[16384,4096] @ gate_w[8,4096]^T
// softmax -> top2 -> normalized weights; aux loss = 0.01*E*sum(f*P)
// Output (float32, flat): weights[T,2] | experts[T,2] | logits[T,8] | aux
//
// This round: 3x the warps (24/SM) with a small register footprint so
// cross-warp scheduling hides DRAM/L1 latency (per-warp overlap tricks
// failed for 5 designs in a row; warps/SM was the untouched variable).
// ---------------------------------------------------------------------------

#define T_TOK     16384
#define HDIM      4096
#define NEXP      8
#define TOK_WARP  2
#define NWARP     8
#define NTHREAD   256
#define TOK_BLK   (TOK_WARP * NWARP)    /* 16 */
#define NBLOCK    (T_TOK / TOK_BLK)     /* 1024 */
#define CHUNK     256
#define NCHUNK    (HDIM / CHUNK)        /* 16 */

#define OUT_W     0
#define OUT_IDX   (T_TOK * 2)
#define OUT_LOG   (T_TOK * 4)
#define OUT_AUX   (T_TOK * 12)

// Tie tolerance + Kahan logits are a proven pair (R5/R7/R9-R13 pass; without
// Kahan one knife-edge token flips). Per-token arithmetic below is
// bit-identical to those passing kernels (same chunk order, lane mapping,
// Kahan ops, fp64 tree).
#define TIE_TOL   5e-7f

__device__ float    g_Psum[NEXP];
__device__ unsigned g_Cnt[NEXP];
__device__ unsigned g_done;

__global__ void __launch_bounds__(NTHREAD, 3) router_main_kernel(
    const float* __restrict__ hs,    // [T, H]
    const float* __restrict__ gw,    // [E, H]
    float* __restrict__ out)
{
    __shared__ float    sPsum[NEXP];
    __shared__ unsigned sCnt[NEXP];

    const int tid  = threadIdx.x;
    const int warp = tid >> 5;
    const int lane = tid & 31;
    const int row0 = warp * TOK_WARP;
    const size_t tokBase = (size_t)blockIdx.x * TOK_BLK;

    if (tid < NEXP) { sPsum[tid] = 0.0f; sCnt[tid] = 0u; }
    __syncthreads();

    // Kahan-compensated fp32 accumulators per (expert, token)
    float accS[NEXP][TOK_WARP];
    float accC[NEXP][TOK_WARP];
    #pragma unroll
    for (int e = 0; e < NEXP; e++)
        #pragma unroll
        for (int t = 0; t < TOK_WARP; t++) { accS[e][t] = 0.0f; accC[e][t] = 0.0f; }

    const float* hp = hs + (tokBase + row0) * HDIM + lane * 4;

    #pragma unroll 2
    for (int c = 0; c < NCHUNK; c++) {
        // hidden: batch the 4 LDG.128 (streaming hint -> L1 stays gate's)
        float4 xa[TOK_WARP], xb[TOK_WARP];
        {
            const float* hc = hp + c * CHUNK;
            #pragma unroll
            for (int t = 0; t < TOK_WARP; t++) {
                xa[t] = __ldcs((const float4*)(hc + (size_t)t * HDIM));
                xb[t] = __ldcs((const float4*)(hc + (size_t)t * HDIM + 128));
            }
        }

        // per-expert gate load (L1-resident), reused across both tokens
        const float* gp = gw + c * CHUNK + lane * 4;
        #pragma unroll
        for (int e = 0; e < NEXP; e++) {
            const float4 g0 = *(const float4*)(gp + e * HDIM);
            const float4 g1 = *(const float4*)(gp + e * HDIM + 128);
            #pragma unroll
            for (int t = 0; t < TOK_WARP; t++) {
                float p = __fmul_rn(xa[t].x, g0.x);
                p = __fmaf_rn(xa[t].y, g0.y, p);
                p = __fmaf_rn(xa[t].z, g0.z, p);
                p = __fmaf_rn(xa[t].w, g0.w, p);
                p = __fmaf_rn(xb[t].x, g1.x, p);
                p = __fmaf_rn(xb[t].y, g1.y, p);
                p = __fmaf_rn(xb[t].z, g1.z, p);
                p = __fmaf_rn(xb[t].w, g1.w, p);
                float y  = __fsub_rn(p, accC[e][t]);
                float t2 = __fadd_rn(accS[e][t], y);
                accC[e][t] = __fsub_rn(__fsub_rn(t2, accS[e][t]), y);
                accS[e][t] = t2;
            }
        }
    }

    // ---- cross-lane reduction in fp64 (exact); owning lane keeps result
    float l[NEXP];
    #pragma unroll
    for (int e = 0; e < NEXP; e++) {
        #pragma unroll
        for (int t = 0; t < TOK_WARP; t++) {
            double v = (double)accS[e][t] + (double)accC[e][t];
            v += __shfl_xor_sync(0xFFFFFFFFu, v, 16);
            v += __shfl_xor_sync(0xFFFFFFFFu, v, 8);
            v += __shfl_xor_sync(0xFFFFFFFFu, v, 4);
            v += __shfl_xor_sync(0xFFFFFFFFu, v, 2);
            v += __shfl_xor_sync(0xFFFFFFFFu, v, 1);
            if (lane == t) l[e] = (float)v;
        }
    }

    // ---- epilogue: lanes 0..1 each finish one token
    if (lane < TOK_WARP) {
        const size_t tok = tokBase + row0 + lane;

        float* lg = out + OUT_LOG + tok * NEXP;
        ((float4*)lg)[0] = make_float4(l[0], l[1], l[2], l[3]);
        ((float4*)lg)[1] = make_float4(l[4], l[5], l[6], l[7]);

        float m = l[0];
        #pragma unroll
        for (int e = 1; e < NEXP; e++) m = fmaxf(m, l[e]);
        float p[NEXP], sum = 0.0f;
        #pragma unroll
        for (int e = 0; e < NEXP; e++) { p[e] = expf(l[e] - m); sum += p[e]; }
        const float inv = 1.0f / sum;

        int i1 = 0;
        #pragma unroll
        for (int e = 1; e < NEXP; e++) if (p[e] > p[i1] + TIE_TOL) i1 = e;
        int i2 = (i1 == 0) ? 1 : 0;
        #pragma unroll
        for (int e = 0; e < NEXP; e++)
            if (e != i1 && e != i2 && p[e] > p[i2] + TIE_TOL) i2 = e;
        const float v1 = p[i1];
        const float v2 = p[i2];

        const float winv = 1.0f / (v1 + v2);
        out[OUT_W   + tok * 2 + 0] = v1 * winv;
        out[OUT_W   + tok * 2 + 1] = v2 * winv;
        out[OUT_IDX + tok * 2 + 0] = (float)i1;
        out[OUT_IDX + tok * 2 + 1] = (float)i2;

        #pragma unroll
        for (int e = 0; e < NEXP; e++) atomicAdd(&sPsum[e], p[e] * inv);
        atomicAdd(&sCnt[i1], 1u);
    }
    __syncthreads();

    // ---- aux-loss: push partials; last block finalizes + resets scratch
    if (tid == 0) {
        #pragma unroll
        for (int e = 0; e < NEXP; e++) {
            atomicAdd(&g_Psum[e], sPsum[e]);
            atomicAdd(&g_Cnt[e],  sCnt[e]);
        }
        __threadfence();
        const unsigned prev = atomicAdd(&g_done, 1u);
        if (prev == NBLOCK - 1) {
            float s = 0.0f;
            const float invT = 1.0f / (float)T_TOK;
            #pragma unroll
            for (int e = 0; e < NEXP; e++) {
                const float P = atomicAdd(&g_Psum[e], 0.0f) * invT;
                const float f = (float)atomicAdd(&g_Cnt[e], 0u) * invT;
                s += f * P;
            }
            out[OUT_AUX] = 0.01f * (float)NEXP * s;
            #pragma unroll
            for (int e = 0; e < NEXP; e++) { g_Psum[e] = 0.0f; g_Cnt[e] = 0u; }
            __threadfence();
            g_done = 0u;
        }
    }
}

extern "C" void kernel_launch(void* const* d_in, const int* in_sizes, int n_in,
                              void* d_out, int out_size) {
    const float* hs = (const float*)d_in[0];
    const float* gw = (const float*)d_in[1];
    if (n_in >= 2 && in_sizes[0] < in_sizes[1]) {
        const float* tmp = hs; hs = gw; gw = tmp;
    }
    float* out = (float*)d_out;

    router_main_kernel<<<NBLOCK, NTHREAD>>>(hs, gw, out);
}